// round 1
// baseline (speedup 1.0000x reference)
#include <cuda_runtime.h>
#include <math.h>

// Problem constants (fixed by the reference)
#define T_TOK 8192      // B*S tokens
#define DIM   1024      // d_model
#define FDIM  4096      // ffn dim
#define TWOF  8192      // 2*FDIM
#define NEXP  8

// ---------------- scratch (device globals; no runtime allocation) ----------
__device__ int   g_idx[T_TOK];
__device__ float g_w[T_TOK];
__device__ int   g_cnt[NEXP];
__device__ float g_ssum[NEXP];
__device__ int   g_tok[NEXP * T_TOK];
__device__ float g_hid[(size_t)T_TOK * FDIM];   // gated hidden activations (128 MB)

// ---------------- init ------------------------------------------------------
__global__ void k_init() {
    int i = threadIdx.x;
    if (i < NEXP) { g_cnt[i] = 0; g_ssum[i] = 0.0f; }
}

// ---------------- gating: logits -> softmax -> top-1, routing lists ---------
__global__ void __launch_bounds__(256) k_gate(const float* __restrict__ x,
                                              const float* __restrict__ Wg,
                                              const float* __restrict__ bg) {
    int warp = threadIdx.x >> 5, lane = threadIdx.x & 31;
    int t = blockIdx.x * 8 + warp;
    if (t >= T_TOK) return;
    const float* xr = x + (size_t)t * DIM;

    float acc[NEXP];
#pragma unroll
    for (int e = 0; e < NEXP; e++) acc[e] = 0.0f;

    for (int d = lane; d < DIM; d += 32) {
        float xv = xr[d];
        const float* wr = Wg + d * NEXP;
#pragma unroll
        for (int e = 0; e < NEXP; e++) acc[e] += xv * wr[e];
    }
#pragma unroll
    for (int e = 0; e < NEXP; e++) {
#pragma unroll
        for (int o = 16; o > 0; o >>= 1)
            acc[e] += __shfl_xor_sync(0xffffffffu, acc[e], o);
    }

    if (lane == 0) {
        float m = -1e30f;
#pragma unroll
        for (int e = 0; e < NEXP; e++) { acc[e] += bg[e]; m = fmaxf(m, acc[e]); }
        float s = 0.0f, p[NEXP];
#pragma unroll
        for (int e = 0; e < NEXP; e++) { p[e] = expf(acc[e] - m); s += p[e]; }
        // argmax on logits, first-index tie-break (matches jnp.argmax)
        int best = 0; float bl = acc[0];
#pragma unroll
        for (int e = 1; e < NEXP; e++) if (acc[e] > bl) { bl = acc[e]; best = e; }
        float w = p[best] / s;
        g_idx[t] = best;
        g_w[t]   = w;
        int pos = atomicAdd(&g_cnt[best], 1);
        g_tok[best * T_TOK + pos] = t;
        atomicAdd(&g_ssum[best], w);
    }
}

// ---------------- utilization loss ------------------------------------------
__global__ void k_loss(float* __restrict__ out, int out_size) {
    if (threadIdx.x == 0 && out_size > T_TOK * DIM) {
        float l = 0.0f;
#pragma unroll
        for (int e = 0; e < NEXP; e++) {
            float u = g_ssum[e] / ((float)g_cnt[e] + 1e-8f);
            float d = u - (1.0f / NEXP);
            l += d * d;
        }
        out[T_TOK * DIM] = l;   // loss is appended after the [B,S,D] tensor
    }
}

// ---------------- GEMM1: h = x @ Wfc[e] + bfc[e]; gated = x1 * gelu(x2) ----
// Block computes a 64-token x 64-col tile of BOTH halves (x1 and x2) so the
// GLU gate fuses into the epilogue. K = DIM = 1024.
#define BM1 64
#define BN1 64
#define BK1 16

__global__ void __launch_bounds__(256) k_ffn1(const float* __restrict__ x,
                                              const float* __restrict__ Wfc,
                                              const float* __restrict__ bfc) {
    int e   = blockIdx.z;
    int cnt = g_cnt[e];
    int m0  = blockIdx.x * BM1;
    if (m0 >= cnt) return;
    int n0  = blockIdx.y * BN1;           // column within [0, FDIM)

    __shared__ float As [BK1][BM1];
    __shared__ float Bs1[BK1][BN1];
    __shared__ float Bs2[BK1][BN1];

    int tid = threadIdx.x;
    int tx  = tid & 15, ty = tid >> 4;

    int lm  = tid >> 2;                   // 0..63 : A row within tile
    int lkq = (tid & 3) * 4;              // 0,4,8,12 : k quad
    int tokA = (m0 + lm < cnt) ? g_tok[e * T_TOK + m0 + lm] : -1;
    const float* arow = x + (size_t)(tokA < 0 ? 0 : tokA) * DIM;

    int bk  = tid >> 4;                   // 0..15
    int bnq = (tid & 15) * 4;             // 0..60
    const float* Bbase = Wfc + (size_t)e * DIM * TWOF;

    float acc1[4][4], acc2[4][4];
#pragma unroll
    for (int i = 0; i < 4; i++)
#pragma unroll
        for (int j = 0; j < 4; j++) { acc1[i][j] = 0.0f; acc2[i][j] = 0.0f; }

    for (int k0 = 0; k0 < DIM; k0 += BK1) {
        float4 av = make_float4(0.f, 0.f, 0.f, 0.f);
        if (tokA >= 0) av = *(const float4*)(arow + k0 + lkq);
        As[lkq + 0][lm] = av.x; As[lkq + 1][lm] = av.y;
        As[lkq + 2][lm] = av.z; As[lkq + 3][lm] = av.w;

        const float* brow = Bbase + (size_t)(k0 + bk) * TWOF;
        *(float4*)&Bs1[bk][bnq] = *(const float4*)(brow + n0 + bnq);
        *(float4*)&Bs2[bk][bnq] = *(const float4*)(brow + FDIM + n0 + bnq);
        __syncthreads();

#pragma unroll
        for (int kk = 0; kk < BK1; kk++) {
            float a[4], b1[4], b2[4];
#pragma unroll
            for (int i = 0; i < 4; i++) a[i]  = As [kk][ty * 4 + i];
#pragma unroll
            for (int j = 0; j < 4; j++) b1[j] = Bs1[kk][tx * 4 + j];
#pragma unroll
            for (int j = 0; j < 4; j++) b2[j] = Bs2[kk][tx * 4 + j];
#pragma unroll
            for (int i = 0; i < 4; i++)
#pragma unroll
                for (int j = 0; j < 4; j++) {
                    acc1[i][j] += a[i] * b1[j];
                    acc2[i][j] += a[i] * b2[j];
                }
        }
        __syncthreads();
    }

    const float* bf1 = bfc + (size_t)e * TWOF + n0;
    const float* bf2 = bf1 + FDIM;
#pragma unroll
    for (int i = 0; i < 4; i++) {
        int m = m0 + ty * 4 + i;
        if (m >= cnt) continue;
        int tok = g_tok[e * T_TOK + m];
        float* hr = g_hid + (size_t)tok * FDIM + n0;
#pragma unroll
        for (int j = 0; j < 4; j++) {
            int n = tx * 4 + j;
            float h1 = acc1[i][j] + bf1[n];
            float h2 = acc2[i][j] + bf2[n];
            float g  = 0.5f * h2 * (1.0f + erff(h2 * 0.70710678118654752f)); // exact gelu
            hr[n] = h1 * g;
        }
    }
}

// ---------------- GEMM2: out = w * (gated @ Wout[e] + bout[e]) --------------
// 64 tokens x 128 cols per block, K = FDIM = 4096.
#define BM2 64
#define BN2 128
#define BK2 16

__global__ void __launch_bounds__(256) k_ffn2(const float* __restrict__ Wout,
                                              const float* __restrict__ bout,
                                              float* __restrict__ out) {
    int e   = blockIdx.z;
    int cnt = g_cnt[e];
    int m0  = blockIdx.x * BM2;
    if (m0 >= cnt) return;
    int n0  = blockIdx.y * BN2;

    __shared__ float As[BK2][BM2];
    __shared__ float Bs[BK2][BN2];

    int tid = threadIdx.x;
    int tx  = tid & 15, ty = tid >> 4;

    int lm  = tid >> 2;
    int lkq = (tid & 3) * 4;
    int tokA = (m0 + lm < cnt) ? g_tok[e * T_TOK + m0 + lm] : -1;
    const float* arow = g_hid + (size_t)(tokA < 0 ? 0 : tokA) * FDIM;

    int bk  = tid >> 4;                   // 0..15
    int bnq = (tid & 15) * 8;             // 0..120
    const float* Bbase = Wout + (size_t)e * FDIM * DIM;

    float acc[4][8];
#pragma unroll
    for (int i = 0; i < 4; i++)
#pragma unroll
        for (int j = 0; j < 8; j++) acc[i][j] = 0.0f;

    for (int k0 = 0; k0 < FDIM; k0 += BK2) {
        float4 av = make_float4(0.f, 0.f, 0.f, 0.f);
        if (tokA >= 0) av = *(const float4*)(arow + k0 + lkq);
        As[lkq + 0][lm] = av.x; As[lkq + 1][lm] = av.y;
        As[lkq + 2][lm] = av.z; As[lkq + 3][lm] = av.w;

        const float* brow = Bbase + (size_t)(k0 + bk) * DIM + n0;
        *(float4*)&Bs[bk][bnq]     = *(const float4*)(brow + bnq);
        *(float4*)&Bs[bk][bnq + 4] = *(const float4*)(brow + bnq + 4);
        __syncthreads();

#pragma unroll
        for (int kk = 0; kk < BK2; kk++) {
            float a[4], b[8];
#pragma unroll
            for (int i = 0; i < 4; i++) a[i] = As[kk][ty * 4 + i];
#pragma unroll
            for (int j = 0; j < 8; j++) b[j] = Bs[kk][tx * 8 + j];
#pragma unroll
            for (int i = 0; i < 4; i++)
#pragma unroll
                for (int j = 0; j < 8; j++) acc[i][j] += a[i] * b[j];
        }
        __syncthreads();
    }

    const float* bo = bout + (size_t)e * DIM + n0;
#pragma unroll
    for (int i = 0; i < 4; i++) {
        int m = m0 + ty * 4 + i;
        if (m >= cnt) continue;
        int tok = g_tok[e * T_TOK + m];
        float w = g_w[tok];
        float* orow = out + (size_t)tok * DIM + n0;
#pragma unroll
        for (int j = 0; j < 8; j++) {
            int n = tx * 8 + j;
            orow[n] = w * (acc[i][j] + bo[n]);
        }
    }
}

// ---------------- launch -----------------------------------------------------
extern "C" void kernel_launch(void* const* d_in, const int* in_sizes, int n_in,
                              void* d_out, int out_size) {
    const float* x    = (const float*)d_in[0];
    const float* Wg   = (const float*)d_in[1];
    const float* bg   = (const float*)d_in[2];
    const float* Wfc  = (const float*)d_in[3];
    const float* bfc  = (const float*)d_in[4];
    const float* Wout = (const float*)d_in[5];
    const float* bout = (const float*)d_in[6];
    float* out = (float*)d_out;

    k_init<<<1, 32>>>();
    k_gate<<<T_TOK / 8, 256>>>(x, Wg, bg);
    k_loss<<<1, 32>>>(out, out_size);

    dim3 g1(T_TOK / BM1, FDIM / BN1, NEXP);   // (128, 64, 8) — dead tiles exit early
    k_ffn1<<<g1, 256>>>(x, Wfc, bfc);

    dim3 g2(T_TOK / BM2, DIM / BN2, NEXP);    // (128, 8, 8)
    k_ffn2<<<g2, 256>>>(Wout, bout, out);
}

// round 4
// speedup vs baseline: 2.1997x; 2.1997x over previous
#include <cuda_runtime.h>
#include <cuda_bf16.h>
#include <math.h>
#include <stdint.h>

// Problem constants
#define T_TOK 8192
#define DIM   1024
#define FDIM  4096
#define TWOF  8192
#define NEXP  8

// ---- arch-feature guard: tcgen05 only exists on the sm_103a ("a") target ---
#ifndef __CUDA_ARCH_HAS_FEATURE__
#define __CUDA_ARCH_HAS_FEATURE__(x) 0
#endif
#if defined(__CUDA_ARCH__) && (defined(__CUDA_ARCH_FEAT_SM103_ALL) || __CUDA_ARCH_HAS_FEATURE__(SM103_ALL))
#define TC_PATH 1
#else
#define TC_PATH 0
#endif

// ---------------- common helpers --------------------------------------------
__device__ __forceinline__ uint32_t smem_u32(const void* p) {
    uint32_t a;
    asm("{ .reg .u64 t; cvta.to.shared.u64 t, %1; cvt.u32.u64 %0, t; }" : "=r"(a) : "l"(p));
    return a;
}
__device__ __forceinline__ void mbar_init(uint32_t a, uint32_t cnt) {
    asm volatile("mbarrier.init.shared.b64 [%0], %1;" :: "r"(a), "r"(cnt) : "memory");
}
__device__ __forceinline__ void mbar_inval(uint32_t a) {
    asm volatile("mbarrier.inval.shared.b64 [%0];" :: "r"(a) : "memory");
}
__device__ __forceinline__ void mbar_wait(uint32_t a, uint32_t parity) {
    asm volatile("{\n\t.reg .pred P;\n\tWL_%=:\n\t"
                 "mbarrier.try_wait.parity.shared.b64 P, [%0], %1;\n\t"
                 "@!P bra WL_%=;\n\t}" :: "r"(a), "r"(parity) : "memory");
}
__device__ __forceinline__ void sts16(uint32_t addr, uint4 v) {
    asm volatile("st.shared.v4.b32 [%0], {%1,%2,%3,%4};"
                 :: "r"(addr), "r"(v.x), "r"(v.y), "r"(v.z), "r"(v.w));
}
__device__ __forceinline__ uint32_t swz(uint32_t off) { return off ^ ((off >> 3) & 0x70); }

// fallback-path helpers (valid PTX on plain sm_103)
__device__ __forceinline__ void cpa16(uint32_t dst, const void* src, int sz) {
    asm volatile("cp.async.cg.shared.global [%0], [%1], 16, %2;"
                 :: "r"(dst), "l"(src), "r"(sz) : "memory");
}
__device__ __forceinline__ void cpa_commit() {
    asm volatile("cp.async.commit_group;" ::: "memory");
}
__device__ __forceinline__ void ldsm4(uint32_t* r, uint32_t addr) {
    asm volatile("ldmatrix.sync.aligned.m8n8.x4.shared.b16 {%0,%1,%2,%3}, [%4];"
                 : "=r"(r[0]), "=r"(r[1]), "=r"(r[2]), "=r"(r[3]) : "r"(addr));
}
__device__ __forceinline__ void mma16816(float* c, const uint32_t* a, const uint32_t* b) {
    asm volatile("mma.sync.aligned.m16n8k16.row.col.f32.bf16.bf16.f32 "
                 "{%0,%1,%2,%3}, {%4,%5,%6,%7}, {%8,%9}, {%0,%1,%2,%3};"
                 : "+f"(c[0]), "+f"(c[1]), "+f"(c[2]), "+f"(c[3])
                 : "r"(a[0]), "r"(a[1]), "r"(a[2]), "r"(a[3]), "r"(b[0]), "r"(b[1]));
}

#if TC_PATH
__device__ __forceinline__ uint32_t elect_one() {
    uint32_t pred;
    asm volatile("{\n\t.reg .pred p;\n\telect.sync _|p, 0xFFFFFFFF;\n\tselp.b32 %0, 1, 0, p;\n\t}"
                 : "=r"(pred));
    return pred;
}
__device__ __forceinline__ void tmem_alloc(uint32_t dst_smem, uint32_t ncols) {
    asm volatile("tcgen05.alloc.cta_group::1.sync.aligned.shared::cta.b32 [%0], %1;"
                 :: "r"(dst_smem), "r"(ncols) : "memory");
}
__device__ __forceinline__ void tmem_dealloc(uint32_t tmem, uint32_t ncols) {
    asm volatile("tcgen05.relinquish_alloc_permit.cta_group::1.sync.aligned;");
    asm volatile("tcgen05.dealloc.cta_group::1.sync.aligned.b32 %0, %1;" :: "r"(tmem), "r"(ncols));
}
__device__ __forceinline__ void tc_commit(uint32_t mbar) {
    asm volatile("tcgen05.commit.cta_group::1.mbarrier::arrive::one.shared::cluster.b64 [%0];"
                 :: "r"(mbar) : "memory");
}
__device__ __forceinline__ void tc_fence_after()  { asm volatile("tcgen05.fence::after_thread_sync;"  ::: "memory"); }
__device__ __forceinline__ void tc_fence_before() { asm volatile("tcgen05.fence::before_thread_sync;" ::: "memory"); }
__device__ __forceinline__ void fence_async_smem(){ asm volatile("fence.proxy.async.shared::cta;" ::: "memory"); }
__device__ __forceinline__ void tc_wait_ld()      { asm volatile("tcgen05.wait::ld.sync.aligned;" ::: "memory"); }
__device__ __forceinline__ void ldtm32(uint32_t* r, uint32_t tmem_addr) {
    asm volatile(
        "tcgen05.ld.sync.aligned.32x32b.x32.b32 "
        "{%0,%1,%2,%3,%4,%5,%6,%7,%8,%9,%10,%11,%12,%13,%14,%15,"
        "%16,%17,%18,%19,%20,%21,%22,%23,%24,%25,%26,%27,%28,%29,%30,%31}, [%32];"
        : "=r"(r[0]), "=r"(r[1]), "=r"(r[2]), "=r"(r[3]), "=r"(r[4]), "=r"(r[5]), "=r"(r[6]), "=r"(r[7]),
          "=r"(r[8]), "=r"(r[9]), "=r"(r[10]), "=r"(r[11]), "=r"(r[12]), "=r"(r[13]), "=r"(r[14]), "=r"(r[15]),
          "=r"(r[16]), "=r"(r[17]), "=r"(r[18]), "=r"(r[19]), "=r"(r[20]), "=r"(r[21]), "=r"(r[22]), "=r"(r[23]),
          "=r"(r[24]), "=r"(r[25]), "=r"(r[26]), "=r"(r[27]), "=r"(r[28]), "=r"(r[29]), "=r"(r[30]), "=r"(r[31])
        : "r"(tmem_addr));
}
__device__ __forceinline__ void mma_bf16_ss(uint32_t d, uint64_t a, uint64_t b,
                                            uint32_t idesc, uint32_t acc) {
    asm volatile(
        "{\n\t.reg .pred p;\n\tsetp.ne.u32 p, %5, 0;\n\t"
        "tcgen05.mma.cta_group::1.kind::f16 [%0], %1, %2, %3, {%4,%4,%4,%4}, p;\n\t}"
        :: "r"(d), "l"(a), "l"(b), "r"(idesc), "r"(0u), "r"(acc) : "memory");
}
#define DESC_BASE ((2ull << 61) | (1ull << 46) | (64ull << 32) | (1ull << 16))
__device__ __forceinline__ uint64_t mk_desc(uint32_t addr) {
    return DESC_BASE | ((uint64_t)(addr >> 4) & 0x3FFF);
}
// dtype=F32<<4, atype=BF16<<7, btype=BF16<<10, N/8<<17, M/16<<24  (M=128,N=128)
#define IDESC_128x128 ((1u << 4) | (1u << 7) | (1u << 10) | ((128u / 8) << 17) | ((128u / 16) << 24))
#endif // TC_PATH

// ---------------- scratch (device globals) ----------------------------------
__device__ float g_w[T_TOK];
__device__ int   g_cnt[NEXP];
__device__ float g_ssum[NEXP];
__device__ int   g_tok[NEXP * T_TOK];

__device__ __nv_bfloat16 s_xhi[T_TOK * DIM];
__device__ __nv_bfloat16 s_xlo[T_TOK * DIM];
__device__ __nv_bfloat16 s_w1hi[(size_t)NEXP * TWOF * DIM];   // [e][n(8192)][d] K-major
__device__ __nv_bfloat16 s_w1lo[(size_t)NEXP * TWOF * DIM];
__device__ __nv_bfloat16 s_w2hi[(size_t)NEXP * DIM * FDIM];   // [e][d_out][f] K-major
__device__ __nv_bfloat16 s_w2lo[(size_t)NEXP * DIM * FDIM];
__device__ __nv_bfloat16 s_ghi[(size_t)T_TOK * FDIM];
__device__ __nv_bfloat16 s_glo[(size_t)T_TOK * FDIM];

// ---------------- init / gating / loss --------------------------------------
__global__ void k_init() {
    int i = threadIdx.x;
    if (i < NEXP) { g_cnt[i] = 0; g_ssum[i] = 0.0f; }
}

__global__ void __launch_bounds__(256) k_gate(const float* __restrict__ x,
                                              const float* __restrict__ Wg,
                                              const float* __restrict__ bg) {
    int warp = threadIdx.x >> 5, lane = threadIdx.x & 31;
    int t = blockIdx.x * 8 + warp;
    if (t >= T_TOK) return;
    const float* xr = x + (size_t)t * DIM;
    float acc[NEXP];
#pragma unroll
    for (int e = 0; e < NEXP; e++) acc[e] = 0.0f;
    for (int d = lane; d < DIM; d += 32) {
        float xv = xr[d];
        const float* wr = Wg + d * NEXP;
#pragma unroll
        for (int e = 0; e < NEXP; e++) acc[e] += xv * wr[e];
    }
#pragma unroll
    for (int e = 0; e < NEXP; e++) {
#pragma unroll
        for (int o = 16; o > 0; o >>= 1) acc[e] += __shfl_xor_sync(0xffffffffu, acc[e], o);
    }
    if (lane == 0) {
        float m = -1e30f;
#pragma unroll
        for (int e = 0; e < NEXP; e++) { acc[e] += bg[e]; m = fmaxf(m, acc[e]); }
        float s = 0.0f, p[NEXP];
#pragma unroll
        for (int e = 0; e < NEXP; e++) { p[e] = expf(acc[e] - m); s += p[e]; }
        int best = 0; float bl = acc[0];
#pragma unroll
        for (int e = 1; e < NEXP; e++) if (acc[e] > bl) { bl = acc[e]; best = e; }
        float w = p[best] / s;
        g_w[t] = w;
        int pos = atomicAdd(&g_cnt[best], 1);
        g_tok[best * T_TOK + pos] = t;
        atomicAdd(&g_ssum[best], w);
    }
}

__global__ void k_loss(float* __restrict__ out, int out_size) {
    if (threadIdx.x == 0 && out_size > T_TOK * DIM) {
        float l = 0.0f;
#pragma unroll
        for (int e = 0; e < NEXP; e++) {
            float u = g_ssum[e] / ((float)g_cnt[e] + 1e-8f);
            float d = u - (1.0f / NEXP);
            l += d * d;
        }
        out[T_TOK * DIM] = l;
    }
}

// ---------------- fp32 -> bf16 hi/lo conversions ------------------------------
__global__ void __launch_bounds__(256) k_cvt_x(const float* __restrict__ x) {
    size_t i = ((size_t)blockIdx.x * 256 + threadIdx.x) * 4;
    if (i >= (size_t)T_TOK * DIM) return;
    float4 v = *(const float4*)(x + i);
    __nv_bfloat16 h0 = __float2bfloat16_rn(v.x), h1 = __float2bfloat16_rn(v.y);
    __nv_bfloat16 h2 = __float2bfloat16_rn(v.z), h3 = __float2bfloat16_rn(v.w);
    s_xhi[i] = h0; s_xhi[i + 1] = h1; s_xhi[i + 2] = h2; s_xhi[i + 3] = h3;
    s_xlo[i]     = __float2bfloat16_rn(v.x - __bfloat162float(h0));
    s_xlo[i + 1] = __float2bfloat16_rn(v.y - __bfloat162float(h1));
    s_xlo[i + 2] = __float2bfloat16_rn(v.z - __bfloat162float(h2));
    s_xlo[i + 3] = __float2bfloat16_rn(v.w - __bfloat162float(h3));
}

// Transpose+convert [E][R][C] fp32 -> [E][C][R] bf16 hi/lo
__global__ void __launch_bounds__(256) k_cvt_w(const float* __restrict__ W,
                                               __nv_bfloat16* __restrict__ hi,
                                               __nv_bfloat16* __restrict__ lo,
                                               int R, int C) {
    __shared__ float tile[32][33];
    int e = blockIdx.z;
    int c0 = blockIdx.x * 32, r0 = blockIdx.y * 32;
    int tx = threadIdx.x & 31, ty = threadIdx.x >> 5;   // 32 x 8
    const float* Wb = W + (size_t)e * R * C;
#pragma unroll
    for (int i = 0; i < 4; i++) {
        int r = r0 + ty + i * 8;
        tile[ty + i * 8][tx] = Wb[(size_t)r * C + c0 + tx];
    }
    __syncthreads();
    size_t ob = (size_t)e * (size_t)C * R;
#pragma unroll
    for (int i = 0; i < 4; i++) {
        int c = c0 + ty + i * 8;
        float v = tile[tx][ty + i * 8];
        __nv_bfloat16 h = __float2bfloat16_rn(v);
        hi[ob + (size_t)c * R + r0 + tx] = h;
        lo[ob + (size_t)c * R + r0 + tx] = __float2bfloat16_rn(v - __bfloat162float(h));
    }
}

// ---------------- GEMM kernels ------------------------------------------------
// Both paths: CTA computes a 128-token x 128-col tile.
// GEMM1: B rows interleaved (even row = W1 half1 col n, odd = half2 col n) so
// each output col pair (2p, 2p+1) = (h1[p], h2[p]) -> GLU fused in epilogue.
#define FB_STRIDE 144
#define FB_TILE   (128 * FB_STRIDE)          // 18432 B
#define TC_TILE   16384                      // 128 x 128B SW128
#define SMEM_DYN  (8 * FB_TILE)              // 147456 (covers both paths)

__global__ void __launch_bounds__(256, 1) k_ffn1(const float* __restrict__ bfc) {
    extern __shared__ char dsm[];
    int e = blockIdx.z;
    int cnt = g_cnt[e];
    int m0 = blockIdx.x * 128;
    if (m0 >= cnt) return;
    int n0g = blockIdx.y * 64;               // gated-col base
    int tid = threadIdx.x, wid = tid >> 5, lid = tid & 31;
    uint32_t sb0 = smem_u32(dsm);

#if TC_PATH
    uint32_t ctrl = sb0;
    uint32_t tiles = (sb0 + 1024) & ~1023u;
    if (tid == 0) { mbar_init(ctrl + 8, 1); mbar_init(ctrl + 16, 1); }
    if (wid == 0) tmem_alloc(ctrl, 128);
    __syncthreads();
    uint32_t tm;
    asm volatile("ld.shared.b32 %0, [%1];" : "=r"(tm) : "r"(ctrl));

    int r = tid & 127, part = tid >> 7;
    int tokL = (m0 + r < cnt) ? g_tok[e * T_TOK + m0 + r] : -1;
    const __nv_bfloat16* aH = s_xhi + (size_t)(tokL < 0 ? 0 : tokL) * DIM;
    const __nv_bfloat16* aL = s_xlo + (size_t)(tokL < 0 ? 0 : tokL) * DIM;
    size_t bro = (size_t)e * TWOF + (size_t)(r & 1) * FDIM + n0g + (r >> 1);
    const __nv_bfloat16* bH = s_w1hi + bro * DIM;
    const __nv_bfloat16* bL = s_w1lo + bro * DIM;

    uint32_t ph0 = 0, ph1 = 0;
    for (int it = 0; it < DIM / 64; it++) {
        int k0 = it * 64, buf = it & 1;
        uint32_t st = tiles + buf * 4 * TC_TILE;
        if (it >= 2) {
            if (buf == 0) { mbar_wait(ctrl + 8, ph0); ph0 ^= 1; }
            else          { mbar_wait(ctrl + 16, ph1); ph1 ^= 1; }
        }
#pragma unroll
        for (int i = 0; i < 4; i++) {
            int c = part * 4 + i;
            uint32_t so = swz((uint32_t)(r * 128 + c * 16));
            uint4 z = make_uint4(0, 0, 0, 0);
            sts16(st + 0 * TC_TILE + so, tokL >= 0 ? __ldg((const uint4*)(aH + k0) + c) : z);
            sts16(st + 1 * TC_TILE + so, tokL >= 0 ? __ldg((const uint4*)(aL + k0) + c) : z);
            sts16(st + 2 * TC_TILE + so, __ldg((const uint4*)(bH + k0) + c));
            sts16(st + 3 * TC_TILE + so, __ldg((const uint4*)(bL + k0) + c));
        }
        fence_async_smem();
        __syncthreads();
        if (wid == 0 && elect_one()) {
            uint64_t dAh = mk_desc(st), dAl = mk_desc(st + TC_TILE);
            uint64_t dBh = mk_desc(st + 2 * TC_TILE), dBl = mk_desc(st + 3 * TC_TILE);
#pragma unroll
            for (int kk = 0; kk < 4; kk++) {
                uint32_t first = (it == 0 && kk == 0) ? 0u : 1u;
                uint64_t o = (uint64_t)(kk * 2);
                mma_bf16_ss(tm, dAh + o, dBh + o, IDESC_128x128, first);
                mma_bf16_ss(tm, dAl + o, dBh + o, IDESC_128x128, 1u);
                mma_bf16_ss(tm, dAh + o, dBl + o, IDESC_128x128, 1u);
            }
            tc_commit(buf == 0 ? ctrl + 8 : ctrl + 16);
        }
    }
    mbar_wait(ctrl + 8, ph0);
    mbar_wait(ctrl + 16, ph1);
    tc_fence_after();

    int sg = wid & 3, gg = wid >> 2;
    int mrow = sg * 32 + lid;
    int rtok = (m0 + mrow < cnt) ? g_tok[e * T_TOK + m0 + mrow] : -1;
#pragma unroll
    for (int q = 0; q < 2; q++) {
        int c4 = gg * 2 + q;
        uint32_t rr[32];
        ldtm32(rr, tm + c4 * 32);
        tc_wait_ld();
        if (rtok >= 0) {
            int gb = n0g + c4 * 16;
            const float* f1 = bfc + (size_t)e * TWOF + gb;
            const float* f2 = f1 + FDIM;
            __nv_bfloat16 oh[16], ol[16];
#pragma unroll
            for (int u = 0; u < 16; u++) {
                float h1 = __uint_as_float(rr[2 * u]) + __ldg(f1 + u);
                float h2 = __uint_as_float(rr[2 * u + 1]) + __ldg(f2 + u);
                float gl = 0.5f * h2 * (1.0f + erff(h2 * 0.70710678118654752f));
                float g = h1 * gl;
                __nv_bfloat16 h = __float2bfloat16_rn(g);
                oh[u] = h;
                ol[u] = __float2bfloat16_rn(g - __bfloat162float(h));
            }
            size_t ob = (size_t)rtok * FDIM + gb;
            *(uint4*)(s_ghi + ob) = ((uint4*)oh)[0];
            *(uint4*)(s_ghi + ob + 8) = ((uint4*)oh)[1];
            *(uint4*)(s_glo + ob) = ((uint4*)ol)[0];
            *(uint4*)(s_glo + ob + 8) = ((uint4*)ol)[1];
        }
    }
    tc_fence_before();
    __syncthreads();
    if (tid == 0) { mbar_inval(ctrl + 8); mbar_inval(ctrl + 16); }
    if (wid == 0) tmem_dealloc(tm, 128);

#else  // ---------------- mma.sync fallback ----------------------------------
    const int NIT = DIM / 64;
    int lrow = tid >> 1, lpart = tid & 1;
    int tokL = (m0 + lrow < cnt) ? g_tok[e * T_TOK + m0 + lrow] : -1;
    const char* aH = (const char*)(s_xhi + (size_t)(tokL < 0 ? 0 : tokL) * DIM);
    const char* aL = (const char*)(s_xlo + (size_t)(tokL < 0 ? 0 : tokL) * DIM);
    size_t bro = (size_t)e * TWOF + (size_t)(lrow & 1) * FDIM + n0g + (lrow >> 1);
    const char* bH = (const char*)(s_w1hi + bro * DIM);
    const char* bL = (const char*)(s_w1lo + bro * DIM);
    int asz = (tokL >= 0) ? 16 : 0;
    uint32_t drow = sb0 + lrow * FB_STRIDE;

    auto issue = [&](int buf, int k0) {
        int kb = k0 * 2;
        uint32_t db = drow + buf * 4 * FB_TILE;
#pragma unroll
        for (int i = 0; i < 4; i++) {
            int co = lpart * 64 + i * 16;
            cpa16(db + 0 * FB_TILE + co, aH + kb + co, asz);
            cpa16(db + 1 * FB_TILE + co, aL + kb + co, asz);
            cpa16(db + 2 * FB_TILE + co, bH + kb + co, 16);
            cpa16(db + 3 * FB_TILE + co, bL + kb + co, 16);
        }
        cpa_commit();
    };

    int lane = lid;
    int wm = (wid & 3) * 32, wn = (wid >> 2) * 64;
    int lA_r = (lane & 7) + ((lane >> 3) & 1) * 8, lA_c = lane >> 4;
    int lB_r = (lane & 7) + ((lane >> 4) & 1) * 8, lB_c = (lane >> 3) & 1;

    float acc[2][8][4];
#pragma unroll
    for (int i = 0; i < 2; i++)
#pragma unroll
        for (int j = 0; j < 8; j++)
#pragma unroll
            for (int q = 0; q < 4; q++) acc[i][j][q] = 0.0f;

    issue(0, 0);
    for (int it = 0; it < NIT; it++) {
        if (it + 1 < NIT) {
            issue((it + 1) & 1, (it + 1) * 64);
            asm volatile("cp.async.wait_group 1;" ::: "memory");
        } else {
            asm volatile("cp.async.wait_group 0;" ::: "memory");
        }
        __syncthreads();
        uint32_t Ah = sb0 + (it & 1) * 4 * FB_TILE;
        uint32_t Al = Ah + FB_TILE, Bh = Ah + 2 * FB_TILE, Bl = Ah + 3 * FB_TILE;
#pragma unroll
        for (int k16 = 0; k16 < 4; k16++) {
            uint32_t ah[2][4], al[2][4];
#pragma unroll
            for (int i = 0; i < 2; i++) {
                uint32_t ao = (uint32_t)((wm + i * 16 + lA_r) * FB_STRIDE + (k16 * 2 + lA_c) * 16);
                ldsm4(ah[i], Ah + ao);
                ldsm4(al[i], Al + ao);
            }
            uint32_t bh[8][2], bl[8][2];
#pragma unroll
            for (int j2 = 0; j2 < 4; j2++) {
                uint32_t bo = (uint32_t)((wn + j2 * 16 + lB_r) * FB_STRIDE + (k16 * 2 + lB_c) * 16);
                uint32_t t4[4];
                ldsm4(t4, Bh + bo);
                bh[2 * j2][0] = t4[0]; bh[2 * j2][1] = t4[1];
                bh[2 * j2 + 1][0] = t4[2]; bh[2 * j2 + 1][1] = t4[3];
                ldsm4(t4, Bl + bo);
                bl[2 * j2][0] = t4[0]; bl[2 * j2][1] = t4[1];
                bl[2 * j2 + 1][0] = t4[2]; bl[2 * j2 + 1][1] = t4[3];
            }
#pragma unroll
            for (int i = 0; i < 2; i++)
#pragma unroll
                for (int j = 0; j < 8; j++) {
                    mma16816(acc[i][j], ah[i], bh[j]);
                    mma16816(acc[i][j], al[i], bh[j]);
                    mma16816(acc[i][j], ah[i], bl[j]);
                }
        }
        __syncthreads();
    }

    // epilogue: thread holds (h1,h2) col pairs
#pragma unroll
    for (int i = 0; i < 2; i++) {
        int row0 = wm + i * 16 + (lane >> 2);
        int tok0 = (m0 + row0 < cnt) ? g_tok[e * T_TOK + m0 + row0] : -1;
        int tok1 = (m0 + row0 + 8 < cnt) ? g_tok[e * T_TOK + m0 + row0 + 8] : -1;
#pragma unroll
        for (int j = 0; j < 8; j++) {
            int gcol = n0g + wn / 2 + j * 4 + (lane & 3);
            float b1 = __ldg(bfc + (size_t)e * TWOF + gcol);
            float b2 = __ldg(bfc + (size_t)e * TWOF + FDIM + gcol);
            if (tok0 >= 0) {
                float h1 = acc[i][j][0] + b1, h2 = acc[i][j][1] + b2;
                float g = h1 * (0.5f * h2 * (1.0f + erff(h2 * 0.70710678118654752f)));
                __nv_bfloat16 h = __float2bfloat16_rn(g);
                s_ghi[(size_t)tok0 * FDIM + gcol] = h;
                s_glo[(size_t)tok0 * FDIM + gcol] = __float2bfloat16_rn(g - __bfloat162float(h));
            }
            if (tok1 >= 0) {
                float h1 = acc[i][j][2] + b1, h2 = acc[i][j][3] + b2;
                float g = h1 * (0.5f * h2 * (1.0f + erff(h2 * 0.70710678118654752f)));
                __nv_bfloat16 h = __float2bfloat16_rn(g);
                s_ghi[(size_t)tok1 * FDIM + gcol] = h;
                s_glo[(size_t)tok1 * FDIM + gcol] = __float2bfloat16_rn(g - __bfloat162float(h));
            }
        }
    }
#endif
}

__global__ void __launch_bounds__(256, 1) k_ffn2(const float* __restrict__ bout,
                                                 float* __restrict__ out) {
    extern __shared__ char dsm[];
    int e = blockIdx.z;
    int cnt = g_cnt[e];
    int m0 = blockIdx.x * 128;
    if (m0 >= cnt) return;
    int n0 = blockIdx.y * 128;
    int tid = threadIdx.x, wid = tid >> 5, lid = tid & 31;
    uint32_t sb0 = smem_u32(dsm);

#if TC_PATH
    uint32_t ctrl = sb0;
    uint32_t tiles = (sb0 + 1024) & ~1023u;
    if (tid == 0) { mbar_init(ctrl + 8, 1); mbar_init(ctrl + 16, 1); }
    if (wid == 0) tmem_alloc(ctrl, 128);
    __syncthreads();
    uint32_t tm;
    asm volatile("ld.shared.b32 %0, [%1];" : "=r"(tm) : "r"(ctrl));

    int r = tid & 127, part = tid >> 7;
    int tokL = (m0 + r < cnt) ? g_tok[e * T_TOK + m0 + r] : -1;
    const __nv_bfloat16* aH = s_ghi + (size_t)(tokL < 0 ? 0 : tokL) * FDIM;
    const __nv_bfloat16* aL = s_glo + (size_t)(tokL < 0 ? 0 : tokL) * FDIM;
    const __nv_bfloat16* bH = s_w2hi + ((size_t)e * DIM + n0 + r) * FDIM;
    const __nv_bfloat16* bL = s_w2lo + ((size_t)e * DIM + n0 + r) * FDIM;

    uint32_t ph0 = 0, ph1 = 0;
    for (int it = 0; it < FDIM / 64; it++) {
        int k0 = it * 64, buf = it & 1;
        uint32_t st = tiles + buf * 4 * TC_TILE;
        if (it >= 2) {
            if (buf == 0) { mbar_wait(ctrl + 8, ph0); ph0 ^= 1; }
            else          { mbar_wait(ctrl + 16, ph1); ph1 ^= 1; }
        }
#pragma unroll
        for (int i = 0; i < 4; i++) {
            int c = part * 4 + i;
            uint32_t so = swz((uint32_t)(r * 128 + c * 16));
            uint4 z = make_uint4(0, 0, 0, 0);
            sts16(st + 0 * TC_TILE + so, tokL >= 0 ? __ldg((const uint4*)(aH + k0) + c) : z);
            sts16(st + 1 * TC_TILE + so, tokL >= 0 ? __ldg((const uint4*)(aL + k0) + c) : z);
            sts16(st + 2 * TC_TILE + so, __ldg((const uint4*)(bH + k0) + c));
            sts16(st + 3 * TC_TILE + so, __ldg((const uint4*)(bL + k0) + c));
        }
        fence_async_smem();
        __syncthreads();
        if (wid == 0 && elect_one()) {
            uint64_t dAh = mk_desc(st), dAl = mk_desc(st + TC_TILE);
            uint64_t dBh = mk_desc(st + 2 * TC_TILE), dBl = mk_desc(st + 3 * TC_TILE);
#pragma unroll
            for (int kk = 0; kk < 4; kk++) {
                uint32_t first = (it == 0 && kk == 0) ? 0u : 1u;
                uint64_t o = (uint64_t)(kk * 2);
                mma_bf16_ss(tm, dAh + o, dBh + o, IDESC_128x128, first);
                mma_bf16_ss(tm, dAl + o, dBh + o, IDESC_128x128, 1u);
                mma_bf16_ss(tm, dAh + o, dBl + o, IDESC_128x128, 1u);
            }
            tc_commit(buf == 0 ? ctrl + 8 : ctrl + 16);
        }
    }
    mbar_wait(ctrl + 8, ph0);
    mbar_wait(ctrl + 16, ph1);
    tc_fence_after();

    int sg = wid & 3, gg = wid >> 2;
    int mrow = sg * 32 + lid;
    int rtok = (m0 + mrow < cnt) ? g_tok[e * T_TOK + m0 + mrow] : -1;
    float wtok = (rtok >= 0) ? g_w[rtok] : 0.0f;
#pragma unroll
    for (int q = 0; q < 2; q++) {
        int c4 = gg * 2 + q;
        uint32_t rr[32];
        ldtm32(rr, tm + c4 * 32);
        tc_wait_ld();
        if (rtok >= 0) {
            float ov[32];
            const float* bo = bout + (size_t)e * DIM + n0 + c4 * 32;
#pragma unroll
            for (int j = 0; j < 32; j++)
                ov[j] = wtok * (__uint_as_float(rr[j]) + __ldg(bo + j));
            float* orow = out + (size_t)rtok * DIM + n0 + c4 * 32;
#pragma unroll
            for (int v = 0; v < 8; v++) *(uint4*)(orow + v * 4) = ((uint4*)ov)[v];
        }
    }
    tc_fence_before();
    __syncthreads();
    if (tid == 0) { mbar_inval(ctrl + 8); mbar_inval(ctrl + 16); }
    if (wid == 0) tmem_dealloc(tm, 128);

#else  // ---------------- mma.sync fallback ----------------------------------
    const int NIT = FDIM / 64;
    int lrow = tid >> 1, lpart = tid & 1;
    int tokL = (m0 + lrow < cnt) ? g_tok[e * T_TOK + m0 + lrow] : -1;
    const char* aH = (const char*)(s_ghi + (size_t)(tokL < 0 ? 0 : tokL) * FDIM);
    const char* aL = (const char*)(s_glo + (size_t)(tokL < 0 ? 0 : tokL) * FDIM);
    const char* bH = (const char*)(s_w2hi + ((size_t)e * DIM + n0 + lrow) * FDIM);
    const char* bL = (const char*)(s_w2lo + ((size_t)e * DIM + n0 + lrow) * FDIM);
    int asz = (tokL >= 0) ? 16 : 0;
    uint32_t drow = sb0 + lrow * FB_STRIDE;

    auto issue = [&](int buf, int k0) {
        int kb = k0 * 2;
        uint32_t db = drow + buf * 4 * FB_TILE;
#pragma unroll
        for (int i = 0; i < 4; i++) {
            int co = lpart * 64 + i * 16;
            cpa16(db + 0 * FB_TILE + co, aH + kb + co, asz);
            cpa16(db + 1 * FB_TILE + co, aL + kb + co, asz);
            cpa16(db + 2 * FB_TILE + co, bH + kb + co, 16);
            cpa16(db + 3 * FB_TILE + co, bL + kb + co, 16);
        }
        cpa_commit();
    };

    int lane = lid;
    int wm = (wid & 3) * 32, wn = (wid >> 2) * 64;
    int lA_r = (lane & 7) + ((lane >> 3) & 1) * 8, lA_c = lane >> 4;
    int lB_r = (lane & 7) + ((lane >> 4) & 1) * 8, lB_c = (lane >> 3) & 1;

    float acc[2][8][4];
#pragma unroll
    for (int i = 0; i < 2; i++)
#pragma unroll
        for (int j = 0; j < 8; j++)
#pragma unroll
            for (int q = 0; q < 4; q++) acc[i][j][q] = 0.0f;

    issue(0, 0);
    for (int it = 0; it < NIT; it++) {
        if (it + 1 < NIT) {
            issue((it + 1) & 1, (it + 1) * 64);
            asm volatile("cp.async.wait_group 1;" ::: "memory");
        } else {
            asm volatile("cp.async.wait_group 0;" ::: "memory");
        }
        __syncthreads();
        uint32_t Ah = sb0 + (it & 1) * 4 * FB_TILE;
        uint32_t Al = Ah + FB_TILE, Bh = Ah + 2 * FB_TILE, Bl = Ah + 3 * FB_TILE;
#pragma unroll
        for (int k16 = 0; k16 < 4; k16++) {
            uint32_t ah[2][4], al[2][4];
#pragma unroll
            for (int i = 0; i < 2; i++) {
                uint32_t ao = (uint32_t)((wm + i * 16 + lA_r) * FB_STRIDE + (k16 * 2 + lA_c) * 16);
                ldsm4(ah[i], Ah + ao);
                ldsm4(al[i], Al + ao);
            }
            uint32_t bh[8][2], bl[8][2];
#pragma unroll
            for (int j2 = 0; j2 < 4; j2++) {
                uint32_t bo = (uint32_t)((wn + j2 * 16 + lB_r) * FB_STRIDE + (k16 * 2 + lB_c) * 16);
                uint32_t t4[4];
                ldsm4(t4, Bh + bo);
                bh[2 * j2][0] = t4[0]; bh[2 * j2][1] = t4[1];
                bh[2 * j2 + 1][0] = t4[2]; bh[2 * j2 + 1][1] = t4[3];
                ldsm4(t4, Bl + bo);
                bl[2 * j2][0] = t4[0]; bl[2 * j2][1] = t4[1];
                bl[2 * j2 + 1][0] = t4[2]; bl[2 * j2 + 1][1] = t4[3];
            }
#pragma unroll
            for (int i = 0; i < 2; i++)
#pragma unroll
                for (int j = 0; j < 8; j++) {
                    mma16816(acc[i][j], ah[i], bh[j]);
                    mma16816(acc[i][j], al[i], bh[j]);
                    mma16816(acc[i][j], ah[i], bl[j]);
                }
        }
        __syncthreads();
    }

#pragma unroll
    for (int i = 0; i < 2; i++) {
        int row0 = wm + i * 16 + (lane >> 2);
        int tok0 = (m0 + row0 < cnt) ? g_tok[e * T_TOK + m0 + row0] : -1;
        int tok1 = (m0 + row0 + 8 < cnt) ? g_tok[e * T_TOK + m0 + row0 + 8] : -1;
        float w0 = (tok0 >= 0) ? g_w[tok0] : 0.0f;
        float w1 = (tok1 >= 0) ? g_w[tok1] : 0.0f;
#pragma unroll
        for (int j = 0; j < 8; j++) {
            int col = n0 + wn + j * 8 + 2 * (lane & 3);
            float b0 = __ldg(bout + (size_t)e * DIM + col);
            float b1 = __ldg(bout + (size_t)e * DIM + col + 1);
            if (tok0 >= 0) {
                float2 v = make_float2(w0 * (acc[i][j][0] + b0), w0 * (acc[i][j][1] + b1));
                *(float2*)(out + (size_t)tok0 * DIM + col) = v;
            }
            if (tok1 >= 0) {
                float2 v = make_float2(w1 * (acc[i][j][2] + b0), w1 * (acc[i][j][3] + b1));
                *(float2*)(out + (size_t)tok1 * DIM + col) = v;
            }
        }
    }
#endif
}

// ---------------- launch ------------------------------------------------------
extern "C" void kernel_launch(void* const* d_in, const int* in_sizes, int n_in,
                              void* d_out, int out_size) {
    const float* x    = (const float*)d_in[0];
    const float* Wg   = (const float*)d_in[1];
    const float* bg   = (const float*)d_in[2];
    const float* Wfc  = (const float*)d_in[3];
    const float* bfc  = (const float*)d_in[4];
    const float* Wout = (const float*)d_in[5];
    const float* bout = (const float*)d_in[6];
    float* out = (float*)d_out;

    cudaFuncSetAttribute(k_ffn1, cudaFuncAttributeMaxDynamicSharedMemorySize, SMEM_DYN);
    cudaFuncSetAttribute(k_ffn2, cudaFuncAttributeMaxDynamicSharedMemorySize, SMEM_DYN);

    k_init<<<1, 32>>>();
    k_gate<<<T_TOK / 8, 256>>>(x, Wg, bg);
    k_loss<<<1, 32>>>(out, out_size);

    k_cvt_x<<<(T_TOK * DIM / 4 + 255) / 256, 256>>>(x);
    {
        __nv_bfloat16 *w1h, *w1l, *w2h, *w2l;
        cudaGetSymbolAddress((void**)&w1h, s_w1hi);
        cudaGetSymbolAddress((void**)&w1l, s_w1lo);
        cudaGetSymbolAddress((void**)&w2h, s_w2hi);
        cudaGetSymbolAddress((void**)&w2l, s_w2lo);
        dim3 b(256);
        dim3 gw1(TWOF / 32, DIM / 32, NEXP);
        k_cvt_w<<<gw1, b>>>(Wfc, w1h, w1l, DIM, TWOF);
        dim3 gw2(DIM / 32, FDIM / 32, NEXP);
        k_cvt_w<<<gw2, b>>>(Wout, w2h, w2l, FDIM, DIM);
    }

    dim3 g1(T_TOK / 128, FDIM / 64, NEXP);    // (64, 64, 8)
    k_ffn1<<<g1, 256, SMEM_DYN>>>(bfc);

    dim3 g2(T_TOK / 128, DIM / 128, NEXP);    // (64, 8, 8)
    k_ffn2<<<g2, 256, SMEM_DYN>>>(bout, out);
}